// round 15
// baseline (speedup 1.0000x reference)
#include <cuda_runtime.h>
#include <math.h>

#define SS 256
#define BB 64
#define HH 512
#define EE 300
#define TT 10
#define G4 2048   // 4*H

// ---------------- scratch (static device memory; no allocations) ----------------
__device__ float g_xw2[2][SS][G4][BB];     // input projections, [dir][s][col][b] (268 MB)
__device__ float g_hbk[SS][2][BB][HH];     // h outputs [s][dir][b][k] for K3 (134 MB)
__device__ float g_ht[2][2][HH][BB];       // [dir][parity][k][b] k-major carry (L2-hot)
__device__ float g_c[2][HH][BB];           // c carry [dir][u][b]
__device__ float g_wp[2][HH][G4];          // permuted whh (8 MB, L2-pinned via evict_last)
__device__ float g_feats[BB][SS][TT];      // emissions

__device__ __forceinline__ float sigmf(float x) { return 1.0f / (1.0f + expf(-x)); }

// ---- packed f32x2 helpers (FFMA2: 2 independent fp32 FMAs, bit-exact) ----
__device__ __forceinline__ unsigned long long pack2(float lo, float hi) {
    unsigned long long r;
    asm("mov.b64 %0, {%1, %2};" : "=l"(r) : "f"(lo), "f"(hi));
    return r;
}
__device__ __forceinline__ void fma2(unsigned long long& d, unsigned long long a, unsigned long long b) {
    asm("fma.rn.f32x2 %0, %1, %2, %0;" : "+l"(d) : "l"(a), "l"(b));
}
__device__ __forceinline__ float2 unpack2(unsigned long long v) {
    float lo, hi;
    asm("mov.b64 {%0, %1}, %2;" : "=f"(lo), "=f"(hi) : "l"(v));
    return make_float2(lo, hi);
}
__device__ __forceinline__ unsigned int smem_u32(const void* p) {
    unsigned int a;
    asm("{ .reg .u64 t; cvta.to.shared.u64 t, %1; cvt.u32.u64 %0, t; }" : "=r"(a) : "l"(p));
    return a;
}
__device__ __forceinline__ void cpa16(unsigned int dst, const void* src) {
    asm volatile("cp.async.cg.shared.global [%0], [%1], 16;" :: "r"(dst), "l"(src));
}
// cp.async with L2 evict_last policy (pins weight lines in L2 across launches)
__device__ __forceinline__ void cpa16_pin(unsigned int dst, const void* src,
                                          unsigned long long pol) {
    asm volatile("cp.async.cg.shared.global.L2::cache_hint [%0], [%1], 16, %2;"
                 :: "r"(dst), "l"(src), "l"(pol));
}
__device__ __forceinline__ unsigned long long mk_evict_last() {
    unsigned long long p;
    asm("createpolicy.fractional.L2::evict_last.b64 %0, 1.0;" : "=l"(p));
    return p;
}

// ---------------- K0: permute recurrent weights ----------------
// g_wp[d][k][(u>>1)*8 + q*2 + (u&1)] = whh_d[q*HH + u][k]
__global__ void k0_prep(const float* __restrict__ whh_f, const float* __restrict__ whh_b) {
    const int d = blockIdx.x;
    const int k = blockIdx.y;
    const int u = threadIdx.x;    // 0..511
    const float* w = d ? whh_b : whh_f;
    const int colb = (u >> 1) * 8 + (u & 1);
#pragma unroll
    for (int q = 0; q < 4; q++)
        g_wp[d][k][colb + q * 2] = w[(q * HH + u) * HH + k];
}

// ---------------- K1: fused embedding gather + input projection GEMM ----------------
__global__ __launch_bounds__(256) void k1_proj(
    const int* __restrict__ tokens, const float* __restrict__ emb,
    const float* __restrict__ wih_f, const float* __restrict__ b_f,
    const float* __restrict__ wih_b, const float* __restrict__ b_b)
{
    __shared__ float As[20][68];   // [k][m-local]
    __shared__ float Bs[20][68];   // [k][n-local]

    const int tid = threadIdx.x;
    const int tx = tid & 15, ty = tid >> 4;
    const int n0 = blockIdx.x * 64;
    const int m0 = blockIdx.y * 64;

    const int arow = tid >> 2;            // 0..63
    const int akk  = (tid & 3) * 5;       // 0,5,10,15
    const int m_g  = m0 + arow;
    const int s_g  = m_g >> 6, b_g = m_g & 63;
    int tok = tokens[b_g * SS + s_g];
    if (tok < 0 || tok >= 30000) tok = 0;
    const float* asrc = emb + (long)tok * EE;

    const int bg = n0 + arow;
    const float* wsrc = (bg < G4) ? (wih_f + (long)bg * EE)
                                  : (wih_b + (long)(bg - G4) * EE);

    unsigned long long accp[2][4] = {};

    for (int kt = 0; kt < 15; ++kt) {     // K = 300 = 15 * 20
        const int k0 = kt * 20;
#pragma unroll
        for (int l = 0; l < 5; l++) As[akk + l][arow] = asrc[k0 + akk + l];
#pragma unroll
        for (int l = 0; l < 5; l++) Bs[akk + l][arow] = wsrc[k0 + akk + l];
        __syncthreads();
#pragma unroll
        for (int k = 0; k < 20; k++) {
            ulonglong2 ap = *(const ulonglong2*)&As[k][ty * 4];
            float4 bv = *(const float4*)&Bs[k][tx * 4];
            unsigned long long bp0 = pack2(bv.x, bv.x);
            unsigned long long bp1 = pack2(bv.y, bv.y);
            unsigned long long bp2 = pack2(bv.z, bv.z);
            unsigned long long bp3 = pack2(bv.w, bv.w);
            fma2(accp[0][0], ap.x, bp0); fma2(accp[0][1], ap.x, bp1);
            fma2(accp[0][2], ap.x, bp2); fma2(accp[0][3], ap.x, bp3);
            fma2(accp[1][0], ap.y, bp0); fma2(accp[1][1], ap.y, bp1);
            fma2(accp[1][2], ap.y, bp2); fma2(accp[1][3], ap.y, bp3);
        }
        __syncthreads();
    }

    // epilogue: write g_xw2[dir][s][col(u,q)][b]
#pragma unroll
    for (int j = 0; j < 4; j++) {
        const int g   = n0 + tx * 4 + j;
        const int dir = g >> 11;
        const int gl  = g & 2047;
        const int q   = gl >> 9;
        const int u   = gl & 511;
        const int col = (u >> 1) * 8 + q * 2 + (u & 1);
        const float bias = dir ? b_b[gl] : b_f[gl];
#pragma unroll
        for (int p = 0; p < 2; p++) {
            float2 v = unpack2(accp[p][j]);
            const int mA = m0 + ty * 4 + 2 * p;
            g_xw2[dir][mA >> 6][col][mA & 63]             = v.x + bias;
            g_xw2[dir][(mA + 1) >> 6][col][(mA + 1) & 63] = v.y + bias;
        }
    }
}

// ---------------- K2: one LSTM time step (smem-staged, weights L2-pinned) -----------
// grid (64, 2): blockIdx.y = dir, blockIdx.x = group of 8 units (4 pairs).
// 512 threads: kh = tid>>8 (K half), pp = (tid>>6)&3 (unit pair), j = tid&63 (batch).
// 128 CTAs, 1 CTA/SM (wave-1, balanced), 4 warps/SMSP.
// ONE cp.async stage per step: weights 64 KB (evict_last -> L2-resident after step 1)
// + full-dir h 128 KB. Inner loop is pure LDS + FFMA2.
#define K2_DSMEM ((512 * 32 + 512 * 64) * 4)   // ws + hsm = 196608 bytes

__global__ __launch_bounds__(512, 1) void k2_step(const int* __restrict__ lengths, int t)
{
    extern __shared__ float sm[];
    float (*ws)[32]  = (float (*)[32])sm;            // [k][pp*8 + gate*2 + unit]
    float (*hsm)[64] = (float (*)[64])(sm + 16384);  // [k][b]
    __shared__ float red[4][64][9];                  // [pp][j][8 partials, pad 9]

    const int dir = blockIdx.y;
    const int s   = dir ? (SS - 1 - t) : t;
    const int bx  = blockIdx.x;            // 0..63
    const int tid = threadIdx.x;
    const int kh  = tid >> 8;              // K half
    const int pp  = (tid >> 6) & 3;        // pair in group
    const int j   = tid & 63;              // batch
    const int pg  = bx * 4 + pp;           // global unit pair
    const int u0  = pg * 2;

    const int len = lengths[j];

    // xw gates (kh==0 lanes only; coalesced over b)
    float xwv[8];
    if (kh == 0) {
        const float* xp = &g_xw2[dir][s][pg * 8][j];
#pragma unroll
        for (int i = 0; i < 8; i++) xwv[i] = __ldg(&xp[i * BB]);
    }

    unsigned long long accI = 0, accF = 0, accG = 0, accO = 0;   // (u0, u0+1)

    if (t > 0) {
        // ---- single cp.async stage: weights (64 KB, L2-pinned) + h (128 KB) ----
        {
            const unsigned long long pol = mk_evict_last();
            const unsigned int ws_s  = smem_u32(&ws[0][0]);
            const unsigned int hs_s  = smem_u32(&hsm[0][0]);
            const float* wsrc = &g_wp[dir][0][bx * 32];              // row stride G4
            const float* hsrc = &g_ht[dir][(t & 1) ^ 1][0][0];       // contiguous 128 KB
#pragma unroll
            for (int i = 0; i < 8; i++) {                             // w: 4096 chunks
                const int c = tid + i * 512;
                const int r = c >> 3, c4 = (c & 7) * 4;
                cpa16_pin(ws_s + (r * 32 + c4) * 4, wsrc + (long)r * G4 + c4, pol);
            }
#pragma unroll
            for (int i = 0; i < 16; i++) {                            // h: 8192 chunks
                const int c = tid + i * 512;
                cpa16(hs_s + c * 16, hsrc + c * 4);
            }
            asm volatile("cp.async.commit_group;");
            asm volatile("cp.async.wait_group 0;");
        }
        __syncthreads();

        const float* hh = &hsm[kh * 256][0];
        for (int kt = 0; kt < 16; ++kt) {
#pragma unroll
            for (int kk = 0; kk < 16; ++kk) {
                const int k = kt * 16 + kk;
                const float h = hh[k * 64 + j];                       // 1-wf LDS
                const unsigned long long hp = pack2(h, h);
                const int kw = kh * 256 + k;
                ulonglong2 w01 = *(const ulonglong2*)&ws[kw][pp * 8];       // broadcast
                ulonglong2 w23 = *(const ulonglong2*)&ws[kw][pp * 8 + 4];   // broadcast
                fma2(accI, w01.x, hp);
                fma2(accF, w01.y, hp);
                fma2(accG, w23.x, hp);
                fma2(accO, w23.y, hp);
            }
        }
    }

    // cross-half reduction (fixed order: half0 + half1 -> deterministic)
    const float2 ai = unpack2(accI), af = unpack2(accF);
    const float2 ag = unpack2(accG), ao = unpack2(accO);
    if (kh == 1) {
        red[pp][j][0] = ai.x; red[pp][j][1] = ai.y;
        red[pp][j][2] = af.x; red[pp][j][3] = af.y;
        red[pp][j][4] = ag.x; red[pp][j][5] = ag.y;
        red[pp][j][6] = ao.x; red[pp][j][7] = ao.y;
    }
    __syncthreads();
    if (kh == 0) {
        const float i0 = (ai.x + red[pp][j][0]) + xwv[0];
        const float i1 = (ai.y + red[pp][j][1]) + xwv[1];
        const float f0 = (af.x + red[pp][j][2]) + xwv[2];
        const float f1 = (af.y + red[pp][j][3]) + xwv[3];
        const float g0 = (ag.x + red[pp][j][4]) + xwv[4];
        const float g1 = (ag.y + red[pp][j][5]) + xwv[5];
        const float o0 = (ao.x + red[pp][j][6]) + xwv[6];
        const float o1 = (ao.y + red[pp][j][7]) + xwv[7];

        float c_old0 = 0.f, c_old1 = 0.f;
        if (t > 0) {
            c_old0 = g_c[dir][u0][j];
            c_old1 = g_c[dir][u0 + 1][j];
        }
        const float cn0 = sigmf(f0) * c_old0 + sigmf(i0) * tanhf(g0);
        const float hn0 = sigmf(o0) * tanhf(cn0);
        const float cn1 = sigmf(f1) * c_old1 + sigmf(i1) * tanhf(g1);
        const float hn1 = sigmf(o1) * tanhf(cn1);

        const bool msk = s < len;
        const float hw0 = msk ? hn0 : 0.f;
        const float hw1 = msk ? hn1 : 0.f;
        g_c[dir][u0][j]     = msk ? cn0 : c_old0;      // coalesced over b
        g_c[dir][u0 + 1][j] = msk ? cn1 : c_old1;
        const int wp = t & 1;
        g_ht[dir][wp][u0][j]     = hw0;                // coalesced k-major carry
        g_ht[dir][wp][u0 + 1][j] = hw1;
        *(float2*)&g_hbk[s][dir][j][u0] = make_float2(hw0, hw1);   // K3 layout
    }
}

// ---------------- K3: emissions feats = h @ w_out^T + b_out ----------------
__global__ __launch_bounds__(256) void k3_feats(
    const float* __restrict__ w_out, const float* __restrict__ b_out)
{
    __shared__ float ws[TT * 1024];   // [t][dir*512 + k]
    for (int i = threadIdx.x; i < TT * 1024; i += 256) ws[i] = w_out[i];
    __syncthreads();

    const int widx = blockIdx.x * 8 + (threadIdx.x >> 5);
    const int lane = threadIdx.x & 31;
    const int s = widx >> 6, b = widx & 63;

    float acc[TT];
#pragma unroll
    for (int t = 0; t < TT; t++) acc[t] = 0.0f;

#pragma unroll
    for (int d = 0; d < 2; d++) {
        const float* hrow = &g_hbk[s][d][b][0];
#pragma unroll 4
        for (int i = 0; i < 16; i++) {
            const int k = lane + i * 32;
            const float hv = hrow[k];
#pragma unroll
            for (int t = 0; t < TT; t++) acc[t] += hv * ws[t * 1024 + d * 512 + k];
        }
    }
#pragma unroll
    for (int t = 0; t < TT; t++) {
        float v = acc[t];
        v += __shfl_xor_sync(0xffffffffu, v, 16);
        v += __shfl_xor_sync(0xffffffffu, v, 8);
        v += __shfl_xor_sync(0xffffffffu, v, 4);
        v += __shfl_xor_sync(0xffffffffu, v, 2);
        v += __shfl_xor_sync(0xffffffffu, v, 1);
        if (lane == t) g_feats[b][s][t] = v + b_out[t];
    }
}

// ---------------- K4: Viterbi decode + backtrace (one warp per batch) ----------------
// Output written as float32 (harness __output__ dtype).
__global__ __launch_bounds__(32) void k4_viterbi(
    const float* __restrict__ start_t, const float* __restrict__ end_t,
    const float* __restrict__ trans, const int* __restrict__ lengths,
    float* __restrict__ out)
{
    const int b = blockIdx.x;
    const int lane = threadIdx.x;
    __shared__ float fe[SS][TT];
    __shared__ float tr[TT][TT];
    __shared__ float sc[TT];
    __shared__ unsigned char bp[SS][TT];

    for (int i = lane; i < SS * TT; i += 32)
        ((float*)fe)[i] = ((const float*)g_feats[b])[i];
    for (int i = lane; i < TT * TT; i += 32)
        ((float*)tr)[i] = trans[i];
    int len = lengths[b];
    if (len < 0) len = 0; if (len > SS) len = SS;
    __syncwarp();
    if (lane < TT) sc[lane] = start_t[lane] + fe[0][lane];
    __syncwarp();

    for (int s = 1; s < SS; ++s) {
        float best = -1e30f; int arg = 0;
        if (lane < TT) {
#pragma unroll
            for (int i = 0; i < TT; i++) {
                const float c = sc[i] + tr[i][lane];
                if (c > best) { best = c; arg = i; }   // first-max, matches jnp.argmax
            }
        }
        __syncwarp();
        if (lane < TT) {
            if (s < len) { sc[lane] = best + fe[s][lane]; bp[s][lane] = (unsigned char)arg; }
            else         { bp[s][lane] = (unsigned char)lane; }
        }
        __syncwarp();
    }

    if (lane == 0) {
        float bestv = -1e30f; int last = 0;
        for (int j = 0; j < TT; j++) {
            const float v = sc[j] + end_t[j];
            if (v > bestv) { bestv = v; last = j; }
        }
        int cur = last;
        for (int s = SS - 1; s >= 1; --s) {
            out[b * SS + s] = (float)((s < len) ? cur : 0);
            cur = bp[s][cur];
        }
        out[b * SS + 0] = (float)cur;
    }
}

// ---------------- host ----------------
static int find_slot(const int* sz, int n, int want, int which, int fallback) {
    int seen = 0;
    for (int i = 0; i < n; i++)
        if (sz[i] == want) { if (seen == which) return i; seen++; }
    return fallback;
}

extern "C" void kernel_launch(void* const* d_in, const int* in_sizes, int n_in,
                              void* d_out, int out_size)
{
    const int i_tok  = find_slot(in_sizes, n_in, SS * BB,      0, 0);
    const int i_len  = find_slot(in_sizes, n_in, BB,           0, 1);
    const int i_emb  = find_slot(in_sizes, n_in, 30000 * EE,   0, 2);
    const int i_wif  = find_slot(in_sizes, n_in, G4 * EE,      0, 3);
    const int i_whf  = find_slot(in_sizes, n_in, G4 * HH,      0, 4);
    const int i_bf   = find_slot(in_sizes, n_in, G4,           0, 5);
    const int i_wib  = find_slot(in_sizes, n_in, G4 * EE,      1, 6);
    const int i_whb  = find_slot(in_sizes, n_in, G4 * HH,      1, 7);
    const int i_bb   = find_slot(in_sizes, n_in, G4,           1, 8);
    const int i_wout = find_slot(in_sizes, n_in, TT * 2 * HH,  0, 9);
    const int i_bout = find_slot(in_sizes, n_in, TT,           0, 10);
    const int i_st   = find_slot(in_sizes, n_in, TT,           1, 11);
    const int i_en   = find_slot(in_sizes, n_in, TT,           2, 12);
    const int i_tr   = find_slot(in_sizes, n_in, TT * TT,      0, 13);

    const int*   tokens  = (const int*)  d_in[i_tok];
    const int*   lens    = (const int*)  d_in[i_len];
    const float* emb     = (const float*)d_in[i_emb];
    const float* wih_f   = (const float*)d_in[i_wif];
    const float* whh_f   = (const float*)d_in[i_whf];
    const float* b_f     = (const float*)d_in[i_bf];
    const float* wih_b   = (const float*)d_in[i_wib];
    const float* whh_b   = (const float*)d_in[i_whb];
    const float* b_b     = (const float*)d_in[i_bb];
    const float* w_out   = (const float*)d_in[i_wout];
    const float* b_out   = (const float*)d_in[i_bout];
    const float* start_t = (const float*)d_in[i_st];
    const float* end_t   = (const float*)d_in[i_en];
    const float* trans   = (const float*)d_in[i_tr];
    float* out = (float*)d_out;

    cudaFuncSetAttribute(k2_step, cudaFuncAttributeMaxDynamicSharedMemorySize, K2_DSMEM);

    k0_prep<<<dim3(2, HH), HH>>>(whh_f, whh_b);
    k1_proj<<<dim3(64, 256), 256>>>(tokens, emb, wih_f, b_f, wih_b, b_b);
    for (int t = 0; t < SS; ++t)
        k2_step<<<dim3(64, 2), 512, K2_DSMEM>>>(lens, t);
    k3_feats<<<2048, 256>>>(w_out, b_out);
    k4_viterbi<<<64, 32>>>(start_t, end_t, trans, lens, out);
}

// round 16
// speedup vs baseline: 1.0506x; 1.0506x over previous
#include <cuda_runtime.h>
#include <math.h>

#define SS 256
#define BB 64
#define HH 512
#define EE 300
#define TT 10
#define G4 2048   // 4*H

// ---------------- scratch (static device memory; no allocations) ----------------
__device__ float g_xw2[2][SS][G4][BB];     // input projections, [dir][s][col][b] (268 MB)
__device__ float g_hbk[SS][2][BB][HH];     // h outputs [s][dir][b][k] for K3 (134 MB)
__device__ float g_ht[2][2][HH][BB];       // [dir][parity][k][b] k-major carry (L2-hot)
__device__ float g_wp[2][HH][G4];          // permuted whh: [d][k][(u>>1)*8+q*2+(u&1)] (8 MB)
__device__ float g_feats[BB][SS][TT];      // emissions
__device__ unsigned int g_cnt[8];          // barrier sub-counters
__device__ unsigned int g_root;            // barrier root counter
__device__ unsigned int g_epoch;           // barrier release epoch

__device__ __forceinline__ float sigmf(float x) { return 1.0f / (1.0f + expf(-x)); }

// ---- packed f32x2 helpers (FFMA2: 2 independent fp32 FMAs, bit-exact) ----
__device__ __forceinline__ unsigned long long pack2(float lo, float hi) {
    unsigned long long r;
    asm("mov.b64 %0, {%1, %2};" : "=l"(r) : "f"(lo), "f"(hi));
    return r;
}
__device__ __forceinline__ void fma2(unsigned long long& d, unsigned long long a, unsigned long long b) {
    asm("fma.rn.f32x2 %0, %1, %2, %0;" : "+l"(d) : "l"(a), "l"(b));
}
__device__ __forceinline__ float2 unpack2(unsigned long long v) {
    float lo, hi;
    asm("mov.b64 {%0, %1}, %2;" : "=f"(lo), "=f"(hi) : "l"(v));
    return make_float2(lo, hi);
}
__device__ __forceinline__ unsigned int smem_u32(const void* p) {
    unsigned int a;
    asm("{ .reg .u64 t; cvta.to.shared.u64 t, %1; cvt.u32.u64 %0, t; }" : "=r"(a) : "l"(p));
    return a;
}
__device__ __forceinline__ void cpa16(unsigned int dst, const void* src) {
    asm volatile("cp.async.cg.shared.global [%0], [%1], 16;" :: "r"(dst), "l"(src));
}

// ---------------- K0: permute recurrent weights + reset barrier state ----------------
__global__ void k0_prep(const float* __restrict__ whh_f, const float* __restrict__ whh_b) {
    const int d = blockIdx.x;
    const int k = blockIdx.y;
    const int u = threadIdx.x;    // 0..511
    if (d == 0 && k == 0 && u < 8) g_cnt[u] = 0;
    if (d == 0 && k == 0 && u == 8) { g_root = 0; g_epoch = 0; }
    const float* w = d ? whh_b : whh_f;
    const int colb = (u >> 1) * 8 + (u & 1);
#pragma unroll
    for (int q = 0; q < 4; q++)
        g_wp[d][k][colb + q * 2] = w[(q * HH + u) * HH + k];
}

// ---------------- K1: fused embedding gather + input projection GEMM ----------------
__global__ __launch_bounds__(256) void k1_proj(
    const int* __restrict__ tokens, const float* __restrict__ emb,
    const float* __restrict__ wih_f, const float* __restrict__ b_f,
    const float* __restrict__ wih_b, const float* __restrict__ b_b)
{
    __shared__ float As[20][68];   // [k][m-local]
    __shared__ float Bs[20][68];   // [k][n-local]

    const int tid = threadIdx.x;
    const int tx = tid & 15, ty = tid >> 4;
    const int n0 = blockIdx.x * 64;
    const int m0 = blockIdx.y * 64;

    const int arow = tid >> 2;            // 0..63
    const int akk  = (tid & 3) * 5;       // 0,5,10,15
    const int m_g  = m0 + arow;
    const int s_g  = m_g >> 6, b_g = m_g & 63;
    int tok = tokens[b_g * SS + s_g];
    if (tok < 0 || tok >= 30000) tok = 0;
    const float* asrc = emb + (long)tok * EE;

    const int bg = n0 + arow;
    const float* wsrc = (bg < G4) ? (wih_f + (long)bg * EE)
                                  : (wih_b + (long)(bg - G4) * EE);

    unsigned long long accp[2][4] = {};

    for (int kt = 0; kt < 15; ++kt) {     // K = 300 = 15 * 20
        const int k0 = kt * 20;
#pragma unroll
        for (int l = 0; l < 5; l++) As[akk + l][arow] = asrc[k0 + akk + l];
#pragma unroll
        for (int l = 0; l < 5; l++) Bs[akk + l][arow] = wsrc[k0 + akk + l];
        __syncthreads();
#pragma unroll
        for (int k = 0; k < 20; k++) {
            ulonglong2 ap = *(const ulonglong2*)&As[k][ty * 4];
            float4 bv = *(const float4*)&Bs[k][tx * 4];
            unsigned long long bp0 = pack2(bv.x, bv.x);
            unsigned long long bp1 = pack2(bv.y, bv.y);
            unsigned long long bp2 = pack2(bv.z, bv.z);
            unsigned long long bp3 = pack2(bv.w, bv.w);
            fma2(accp[0][0], ap.x, bp0); fma2(accp[0][1], ap.x, bp1);
            fma2(accp[0][2], ap.x, bp2); fma2(accp[0][3], ap.x, bp3);
            fma2(accp[1][0], ap.y, bp0); fma2(accp[1][1], ap.y, bp1);
            fma2(accp[1][2], ap.y, bp2); fma2(accp[1][3], ap.y, bp3);
        }
        __syncthreads();
    }

    // epilogue: write g_xw2[dir][s][col(u,q)][b]
#pragma unroll
    for (int j = 0; j < 4; j++) {
        const int g   = n0 + tx * 4 + j;
        const int dir = g >> 11;
        const int gl  = g & 2047;
        const int q   = gl >> 9;
        const int u   = gl & 511;
        const int col = (u >> 1) * 8 + q * 2 + (u & 1);
        const float bias = dir ? b_b[gl] : b_f[gl];
#pragma unroll
        for (int p = 0; p < 2; p++) {
            float2 v = unpack2(accp[p][j]);
            const int mA = m0 + ty * 4 + 2 * p;
            g_xw2[dir][mA >> 6][col][mA & 63]             = v.x + bias;
            g_xw2[dir][(mA + 1) >> 6][col][(mA + 1) & 63] = v.y + bias;
        }
    }
}

// ---------------- K2: PERSISTENT LSTM recurrence (all 256 steps, both dirs) ---------
// 128 CTAs (cta = dir*64 + bx), 512 threads, 1 CTA/SM (197 KB smem), all co-resident.
// Thread mapping = R13: kh = tid>>8 (K half), pp = (tid>>6)&3 (unit pair), j = tid&63.
// Weights staged to smem ONCE; h staged per step (cp.async from L2); c carry in regs.
// Cross-CTA step barrier: 8 spread sub-counters -> root -> epoch; thread-0 spin with
// nanosleep backoff; all-thread threadfence before arrive (R5-proven ordering).
#define K2_DSMEM ((512 * 32 + 512 * 64) * 4)   // ws + hsm = 196608 bytes

__global__ __launch_bounds__(512, 1) void k2_persist(const int* __restrict__ lengths)
{
    extern __shared__ float sm[];
    float (*ws)[32]  = (float (*)[32])sm;            // [k][pp*8 + gate*2 + unit]
    float (*hsm)[64] = (float (*)[64])(sm + 16384);  // [k][b]
    __shared__ float red[4][64][9];                  // [pp][j][8 partials, pad 9]

    const int cta = blockIdx.x;            // 0..127
    const int dir = cta >> 6;
    const int bx  = cta & 63;
    const int tid = threadIdx.x;
    const int kh  = tid >> 8;              // K half
    const int pp  = (tid >> 6) & 3;        // pair in group
    const int j   = tid & 63;              // batch
    const int pg  = bx * 4 + pp;           // global unit pair
    const int u0  = pg * 2;

    const int len = lengths[j];
    const unsigned int ws_s = smem_u32(&ws[0][0]);
    const unsigned int hs_s = smem_u32(&hsm[0][0]);

    // ---- stage weights ONCE (64 KB) ----
    {
        const float* wsrc = &g_wp[dir][0][bx * 32];   // row stride G4
#pragma unroll
        for (int i = 0; i < 8; i++) {                  // 4096 float4 chunks
            const int c = tid + i * 512;
            const int r = c >> 3, c4 = (c & 7) * 4;
            cpa16(ws_s + (r * 32 + c4) * 4, wsrc + (long)r * G4 + c4);
        }
        asm volatile("cp.async.commit_group;");
        asm volatile("cp.async.wait_group 0;");
    }
    __syncthreads();

    float c0 = 0.f, c1 = 0.f;              // persistent c carry (kh==0 lanes)

    for (int t = 0; t < SS; ++t) {
        const int s = dir ? (SS - 1 - t) : t;

        // xw gates (kh==0 lanes; issue before h stage so LDG overlaps cp.async)
        float xwv[8];
        if (kh == 0) {
            const float* xp = &g_xw2[dir][s][pg * 8][j];
#pragma unroll
            for (int i = 0; i < 8; i++) xwv[i] = __ldg(&xp[i * BB]);
        }

        unsigned long long accI = 0, accF = 0, accG = 0, accO = 0;   // (u0, u0+1)

        if (t > 0) {
            // ---- stage h (128 KB from L2) ----
            {
                const float* hsrc = &g_ht[dir][(t & 1) ^ 1][0][0];
#pragma unroll
                for (int i = 0; i < 16; i++) {                        // 8192 chunks
                    const int c = tid + i * 512;
                    cpa16(hs_s + c * 16, hsrc + c * 4);
                }
                asm volatile("cp.async.commit_group;");
                asm volatile("cp.async.wait_group 0;");
            }
            __syncthreads();

            const float* hh = &hsm[kh * 256][0];
            for (int kt = 0; kt < 16; ++kt) {
#pragma unroll
                for (int kk = 0; kk < 16; ++kk) {
                    const int k = kt * 16 + kk;
                    const float h = hh[k * 64 + j];                   // 1-wf LDS
                    const unsigned long long hp = pack2(h, h);
                    const int kw = kh * 256 + k;
                    ulonglong2 w01 = *(const ulonglong2*)&ws[kw][pp * 8];       // bcast
                    ulonglong2 w23 = *(const ulonglong2*)&ws[kw][pp * 8 + 4];   // bcast
                    fma2(accI, w01.x, hp);
                    fma2(accF, w01.y, hp);
                    fma2(accG, w23.x, hp);
                    fma2(accO, w23.y, hp);
                }
            }
        }

        // cross-half reduction (fixed order: half0 + half1 -> deterministic)
        const float2 ai = unpack2(accI), af = unpack2(accF);
        const float2 ag = unpack2(accG), ao = unpack2(accO);
        if (kh == 1) {
            red[pp][j][0] = ai.x; red[pp][j][1] = ai.y;
            red[pp][j][2] = af.x; red[pp][j][3] = af.y;
            red[pp][j][4] = ag.x; red[pp][j][5] = ag.y;
            red[pp][j][6] = ao.x; red[pp][j][7] = ao.y;
        }
        __syncthreads();
        if (kh == 0) {
            const float i0 = (ai.x + red[pp][j][0]) + xwv[0];
            const float i1 = (ai.y + red[pp][j][1]) + xwv[1];
            const float f0 = (af.x + red[pp][j][2]) + xwv[2];
            const float f1 = (af.y + red[pp][j][3]) + xwv[3];
            const float g0 = (ag.x + red[pp][j][4]) + xwv[4];
            const float g1 = (ag.y + red[pp][j][5]) + xwv[5];
            const float o0 = (ao.x + red[pp][j][6]) + xwv[6];
            const float o1 = (ao.y + red[pp][j][7]) + xwv[7];

            const float cn0 = sigmf(f0) * c0 + sigmf(i0) * tanhf(g0);
            const float hn0 = sigmf(o0) * tanhf(cn0);
            const float cn1 = sigmf(f1) * c1 + sigmf(i1) * tanhf(g1);
            const float hn1 = sigmf(o1) * tanhf(cn1);

            const bool msk = s < len;
            const float hw0 = msk ? hn0 : 0.f;
            const float hw1 = msk ? hn1 : 0.f;
            c0 = msk ? cn0 : c0;                       // carry in registers
            c1 = msk ? cn1 : c1;
            const int wp = t & 1;
            g_ht[dir][wp][u0][j]     = hw0;            // coalesced k-major carry
            g_ht[dir][wp][u0 + 1][j] = hw1;
            *(float2*)&g_hbk[s][dir][j][u0] = make_float2(hw0, hw1);   // K3 layout
        }

        // ---- cross-CTA step barrier ----
        if (t < SS - 1) {
            __threadfence();
            __syncthreads();
            if (tid == 0) {
                const unsigned int a = atomicAdd(&g_cnt[cta & 7], 1u);
                if ((a & 15u) == 15u) {                       // last of 16 on this counter
                    const unsigned int r = atomicAdd(&g_root, 1u);
                    if ((r & 7u) == 7u)                       // last of 8 sub-counters
                        atomicExch(&g_epoch, (unsigned int)(t + 1));
                }
                while (*(volatile unsigned int*)&g_epoch < (unsigned int)(t + 1))
                    __nanosleep(32);
                __threadfence();
            }
            __syncthreads();
        }
    }
}

// ---------------- K3: emissions feats = h @ w_out^T + b_out ----------------
__global__ __launch_bounds__(256) void k3_feats(
    const float* __restrict__ w_out, const float* __restrict__ b_out)
{
    __shared__ float ws[TT * 1024];   // [t][dir*512 + k]
    for (int i = threadIdx.x; i < TT * 1024; i += 256) ws[i] = w_out[i];
    __syncthreads();

    const int widx = blockIdx.x * 8 + (threadIdx.x >> 5);
    const int lane = threadIdx.x & 31;
    const int s = widx >> 6, b = widx & 63;

    float acc[TT];
#pragma unroll
    for (int t = 0; t < TT; t++) acc[t] = 0.0f;

#pragma unroll
    for (int d = 0; d < 2; d++) {
        const float* hrow = &g_hbk[s][d][b][0];
#pragma unroll 4
        for (int i = 0; i < 16; i++) {
            const int k = lane + i * 32;
            const float hv = hrow[k];
#pragma unroll
            for (int t = 0; t < TT; t++) acc[t] += hv * ws[t * 1024 + d * 512 + k];
        }
    }
#pragma unroll
    for (int t = 0; t < TT; t++) {
        float v = acc[t];
        v += __shfl_xor_sync(0xffffffffu, v, 16);
        v += __shfl_xor_sync(0xffffffffu, v, 8);
        v += __shfl_xor_sync(0xffffffffu, v, 4);
        v += __shfl_xor_sync(0xffffffffu, v, 2);
        v += __shfl_xor_sync(0xffffffffu, v, 1);
        if (lane == t) g_feats[b][s][t] = v + b_out[t];
    }
}

// ---------------- K4: Viterbi decode + backtrace (one warp per batch) ----------------
// Output written as float32 (harness __output__ dtype).
__global__ __launch_bounds__(32) void k4_viterbi(
    const float* __restrict__ start_t, const float* __restrict__ end_t,
    const float* __restrict__ trans, const int* __restrict__ lengths,
    float* __restrict__ out)
{
    const int b = blockIdx.x;
    const int lane = threadIdx.x;
    __shared__ float fe[SS][TT];
    __shared__ float tr[TT][TT];
    __shared__ float sc[TT];
    __shared__ unsigned char bp[SS][TT];

    for (int i = lane; i < SS * TT; i += 32)
        ((float*)fe)[i] = ((const float*)g_feats[b])[i];
    for (int i = lane; i < TT * TT; i += 32)
        ((float*)tr)[i] = trans[i];
    int len = lengths[b];
    if (len < 0) len = 0; if (len > SS) len = SS;
    __syncwarp();
    if (lane < TT) sc[lane] = start_t[lane] + fe[0][lane];
    __syncwarp();

    for (int s = 1; s < SS; ++s) {
        float best = -1e30f; int arg = 0;
        if (lane < TT) {
#pragma unroll
            for (int i = 0; i < TT; i++) {
                const float c = sc[i] + tr[i][lane];
                if (c > best) { best = c; arg = i; }   // first-max, matches jnp.argmax
            }
        }
        __syncwarp();
        if (lane < TT) {
            if (s < len) { sc[lane] = best + fe[s][lane]; bp[s][lane] = (unsigned char)arg; }
            else         { bp[s][lane] = (unsigned char)lane; }
        }
        __syncwarp();
    }

    if (lane == 0) {
        float bestv = -1e30f; int last = 0;
        for (int j = 0; j < TT; j++) {
            const float v = sc[j] + end_t[j];
            if (v > bestv) { bestv = v; last = j; }
        }
        int cur = last;
        for (int s = SS - 1; s >= 1; --s) {
            out[b * SS + s] = (float)((s < len) ? cur : 0);
            cur = bp[s][cur];
        }
        out[b * SS + 0] = (float)cur;
    }
}

// ---------------- host ----------------
static int find_slot(const int* sz, int n, int want, int which, int fallback) {
    int seen = 0;
    for (int i = 0; i < n; i++)
        if (sz[i] == want) { if (seen == which) return i; seen++; }
    return fallback;
}

extern "C" void kernel_launch(void* const* d_in, const int* in_sizes, int n_in,
                              void* d_out, int out_size)
{
    const int i_tok  = find_slot(in_sizes, n_in, SS * BB,      0, 0);
    const int i_len  = find_slot(in_sizes, n_in, BB,           0, 1);
    const int i_emb  = find_slot(in_sizes, n_in, 30000 * EE,   0, 2);
    const int i_wif  = find_slot(in_sizes, n_in, G4 * EE,      0, 3);
    const int i_whf  = find_slot(in_sizes, n_in, G4 * HH,      0, 4);
    const int i_bf   = find_slot(in_sizes, n_in, G4,           0, 5);
    const int i_wib  = find_slot(in_sizes, n_in, G4 * EE,      1, 6);
    const int i_whb  = find_slot(in_sizes, n_in, G4 * HH,      1, 7);
    const int i_bb   = find_slot(in_sizes, n_in, G4,           1, 8);
    const int i_wout = find_slot(in_sizes, n_in, TT * 2 * HH,  0, 9);
    const int i_bout = find_slot(in_sizes, n_in, TT,           0, 10);
    const int i_st   = find_slot(in_sizes, n_in, TT,           1, 11);
    const int i_en   = find_slot(in_sizes, n_in, TT,           2, 12);
    const int i_tr   = find_slot(in_sizes, n_in, TT * TT,      0, 13);

    const int*   tokens  = (const int*)  d_in[i_tok];
    const int*   lens    = (const int*)  d_in[i_len];
    const float* emb     = (const float*)d_in[i_emb];
    const float* wih_f   = (const float*)d_in[i_wif];
    const float* whh_f   = (const float*)d_in[i_whf];
    const float* b_f     = (const float*)d_in[i_bf];
    const float* wih_b   = (const float*)d_in[i_wib];
    const float* whh_b   = (const float*)d_in[i_whb];
    const float* b_b     = (const float*)d_in[i_bb];
    const float* w_out   = (const float*)d_in[i_wout];
    const float* b_out   = (const float*)d_in[i_bout];
    const float* start_t = (const float*)d_in[i_st];
    const float* end_t   = (const float*)d_in[i_en];
    const float* trans   = (const float*)d_in[i_tr];
    float* out = (float*)d_out;

    cudaFuncSetAttribute(k2_persist, cudaFuncAttributeMaxDynamicSharedMemorySize, K2_DSMEM);

    k0_prep<<<dim3(2, HH), HH>>>(whh_f, whh_b);
    k1_proj<<<dim3(64, 256), 256>>>(tokens, emb, wih_f, b_f, wih_b, b_b);
    k2_persist<<<128, 512, K2_DSMEM>>>(lens);
    k3_feats<<<2048, 256>>>(w_out, b_out);
    k4_viterbi<<<64, 32>>>(start_t, end_t, trans, lens, out);
}

// round 17
// speedup vs baseline: 1.2439x; 1.1839x over previous
#include <cuda_runtime.h>
#include <math.h>

#define SS 256
#define BB 64
#define HH 512
#define EE 300
#define TT 10
#define G4 2048   // 4*H

// ---------------- scratch (static device memory; no allocations) ----------------
__device__ float g_xw2[2][SS][G4][BB];     // input projections, [dir][s][col][b] (268 MB)
__device__ float g_hbk[SS][2][BB][HH];     // h outputs [s][dir][b][k] for K3 (134 MB)
__device__ float g_ht[2][2][HH][BB];       // [dir][parity][k][b] k-major carry (L2-hot)
__device__ float g_wp[2][HH][G4];          // permuted whh: [d][k][(u>>1)*8+q*2+(u&1)] (8 MB)
__device__ float g_feats[BB][SS][TT];      // emissions
__device__ unsigned int g_cnt[8];          // barrier sub-counters
__device__ unsigned int g_root;            // barrier root counter
__device__ unsigned int g_epoch;           // barrier release epoch

__device__ __forceinline__ float sigmf(float x) { return 1.0f / (1.0f + expf(-x)); }

// ---- packed f32x2 helpers (FFMA2: 2 independent fp32 FMAs, bit-exact) ----
__device__ __forceinline__ unsigned long long pack2(float lo, float hi) {
    unsigned long long r;
    asm("mov.b64 %0, {%1, %2};" : "=l"(r) : "f"(lo), "f"(hi));
    return r;
}
__device__ __forceinline__ void fma2(unsigned long long& d, unsigned long long a, unsigned long long b) {
    asm("fma.rn.f32x2 %0, %1, %2, %0;" : "+l"(d) : "l"(a), "l"(b));
}
__device__ __forceinline__ float2 unpack2(unsigned long long v) {
    float lo, hi;
    asm("mov.b64 {%0, %1}, %2;" : "=f"(lo), "=f"(hi) : "l"(v));
    return make_float2(lo, hi);
}
__device__ __forceinline__ unsigned int smem_u32(const void* p) {
    unsigned int a;
    asm("{ .reg .u64 t; cvta.to.shared.u64 t, %1; cvt.u32.u64 %0, t; }" : "=r"(a) : "l"(p));
    return a;
}
__device__ __forceinline__ void cpa16(unsigned int dst, const void* src) {
    asm volatile("cp.async.cg.shared.global [%0], [%1], 16;" :: "r"(dst), "l"(src));
}

// ---------------- K0: permute recurrent weights + reset barrier state ----------------
__global__ void k0_prep(const float* __restrict__ whh_f, const float* __restrict__ whh_b) {
    const int d = blockIdx.x;
    const int k = blockIdx.y;
    const int u = threadIdx.x;    // 0..511
    if (d == 0 && k == 0 && u < 8) g_cnt[u] = 0;
    if (d == 0 && k == 0 && u == 8) { g_root = 0; g_epoch = 0; }
    const float* w = d ? whh_b : whh_f;
    const int colb = (u >> 1) * 8 + (u & 1);
#pragma unroll
    for (int q = 0; q < 4; q++)
        g_wp[d][k][colb + q * 2] = w[(q * HH + u) * HH + k];
}

// ---------------- K1: fused embedding gather + input projection GEMM ----------------
__global__ __launch_bounds__(256) void k1_proj(
    const int* __restrict__ tokens, const float* __restrict__ emb,
    const float* __restrict__ wih_f, const float* __restrict__ b_f,
    const float* __restrict__ wih_b, const float* __restrict__ b_b)
{
    __shared__ float As[20][68];   // [k][m-local]
    __shared__ float Bs[20][68];   // [k][n-local]

    const int tid = threadIdx.x;
    const int tx = tid & 15, ty = tid >> 4;
    const int n0 = blockIdx.x * 64;
    const int m0 = blockIdx.y * 64;

    const int arow = tid >> 2;            // 0..63
    const int akk  = (tid & 3) * 5;       // 0,5,10,15
    const int m_g  = m0 + arow;
    const int s_g  = m_g >> 6, b_g = m_g & 63;
    int tok = tokens[b_g * SS + s_g];
    if (tok < 0 || tok >= 30000) tok = 0;
    const float* asrc = emb + (long)tok * EE;

    const int bg = n0 + arow;
    const float* wsrc = (bg < G4) ? (wih_f + (long)bg * EE)
                                  : (wih_b + (long)(bg - G4) * EE);

    unsigned long long accp[2][4] = {};

    for (int kt = 0; kt < 15; ++kt) {     // K = 300 = 15 * 20
        const int k0 = kt * 20;
#pragma unroll
        for (int l = 0; l < 5; l++) As[akk + l][arow] = asrc[k0 + akk + l];
#pragma unroll
        for (int l = 0; l < 5; l++) Bs[akk + l][arow] = wsrc[k0 + akk + l];
        __syncthreads();
#pragma unroll
        for (int k = 0; k < 20; k++) {
            ulonglong2 ap = *(const ulonglong2*)&As[k][ty * 4];
            float4 bv = *(const float4*)&Bs[k][tx * 4];
            unsigned long long bp0 = pack2(bv.x, bv.x);
            unsigned long long bp1 = pack2(bv.y, bv.y);
            unsigned long long bp2 = pack2(bv.z, bv.z);
            unsigned long long bp3 = pack2(bv.w, bv.w);
            fma2(accp[0][0], ap.x, bp0); fma2(accp[0][1], ap.x, bp1);
            fma2(accp[0][2], ap.x, bp2); fma2(accp[0][3], ap.x, bp3);
            fma2(accp[1][0], ap.y, bp0); fma2(accp[1][1], ap.y, bp1);
            fma2(accp[1][2], ap.y, bp2); fma2(accp[1][3], ap.y, bp3);
        }
        __syncthreads();
    }

    // epilogue: write g_xw2[dir][s][col(u,q)][b]
#pragma unroll
    for (int j = 0; j < 4; j++) {
        const int g   = n0 + tx * 4 + j;
        const int dir = g >> 11;
        const int gl  = g & 2047;
        const int q   = gl >> 9;
        const int u   = gl & 511;
        const int col = (u >> 1) * 8 + q * 2 + (u & 1);
        const float bias = dir ? b_b[gl] : b_f[gl];
#pragma unroll
        for (int p = 0; p < 2; p++) {
            float2 v = unpack2(accp[p][j]);
            const int mA = m0 + ty * 4 + 2 * p;
            g_xw2[dir][mA >> 6][col][mA & 63]             = v.x + bias;
            g_xw2[dir][(mA + 1) >> 6][col][(mA + 1) & 63] = v.y + bias;
        }
    }
}

// ---------------- K2: PERSISTENT LSTM (batch-paired FFMA2, 4-way K-split) -----------
// 128 CTAs (cta = dir*64 + bx), 512 threads, 1 CTA/SM, all co-resident.
// Thread: kq = tid>>7 (K quarter, 128 k), pp = (tid>>5)&3 (unit pair), jp = tid&31
// (batch pair b0=2jp, b1=2jp+1). Per k: 1 LDS.64(h) + 2 LDS.128(w bcast) + 2 packs
// + 8 FFMA2 = 13 instr / 16 FMA. Weights staged once; c carry in regs (kq0);
// 4-way reduction via transposed smem, fixed order q0+q1+q2+q3.
#define K2_DSMEM ((512 * 32 + 512 * 64) * 4)   // ws + hsm = 196608 bytes

__global__ __launch_bounds__(512, 1) void k2_persist(const int* __restrict__ lengths)
{
    extern __shared__ float sm[];
    float (*ws)[32]  = (float (*)[32])sm;            // [k][pp*8 + gate*2 + unit]
    float (*hsm)[64] = (float (*)[64])(sm + 16384);  // [k][b]
    __shared__ float red[3][16][4][32];              // [q-1][i][pp][jp]  24 KB

    const int cta = blockIdx.x;            // 0..127
    const int dir = cta >> 6;
    const int bx  = cta & 63;
    const int tid = threadIdx.x;
    const int kq  = tid >> 7;              // K quarter 0..3
    const int pp  = (tid >> 5) & 3;        // pair in group
    const int jp  = tid & 31;              // batch pair
    const int b0  = 2 * jp, b1 = b0 + 1;
    const int pg  = bx * 4 + pp;           // global unit pair
    const int u0  = pg * 2;

    const int len0 = lengths[b0];
    const int len1 = lengths[b1];
    const unsigned int ws_s = smem_u32(&ws[0][0]);
    const unsigned int hs_s = smem_u32(&hsm[0][0]);

    // ---- stage weights ONCE (64 KB) ----
    {
        const float* wsrc = &g_wp[dir][0][bx * 32];   // row stride G4
#pragma unroll
        for (int i = 0; i < 8; i++) {                  // 4096 float4 chunks
            const int c = tid + i * 512;
            const int r = c >> 3, c4 = (c & 7) * 4;
            cpa16(ws_s + (r * 32 + c4) * 4, wsrc + (long)r * G4 + c4);
        }
        asm volatile("cp.async.commit_group;");
        asm volatile("cp.async.wait_group 0;");
    }
    __syncthreads();

    float c00 = 0.f, c01 = 0.f, c10 = 0.f, c11 = 0.f;   // c[un][bt], kq0 lanes

    for (int t = 0; t < SS; ++t) {
        const int s = dir ? (SS - 1 - t) : t;

        // xw gates (kq==0 lanes; 16 loads, issued before h stage to overlap DRAM)
        float xwv[16];                                   // [g*4 + un*2 + bt]
        if (kq == 0) {
            const float* xp = &g_xw2[dir][s][pg * 8][0];
#pragma unroll
            for (int g = 0; g < 4; g++)
#pragma unroll
                for (int un = 0; un < 2; un++) {
                    xwv[g * 4 + un * 2 + 0] = __ldg(&xp[(g * 2 + un) * BB + b0]);
                    xwv[g * 4 + un * 2 + 1] = __ldg(&xp[(g * 2 + un) * BB + b1]);
                }
        }

        // acc[gate][batch] packed over (u0,u1)
        unsigned long long aI0 = 0, aI1 = 0, aF0 = 0, aF1 = 0;
        unsigned long long aG0 = 0, aG1 = 0, aO0 = 0, aO1 = 0;

        if (t > 0) {
            // ---- stage h (128 KB from L2) ----
            {
                const float* hsrc = &g_ht[dir][(t & 1) ^ 1][0][0];
#pragma unroll
                for (int i = 0; i < 16; i++) {                        // 8192 chunks
                    const int c = tid + i * 512;
                    cpa16(hs_s + c * 16, hsrc + c * 4);
                }
                asm volatile("cp.async.commit_group;");
                asm volatile("cp.async.wait_group 0;");
            }
            __syncthreads();

            const float* hh = &hsm[kq * 128][0];
            for (int kt = 0; kt < 8; ++kt) {
#pragma unroll
                for (int kk = 0; kk < 16; ++kk) {
                    const int k = kt * 16 + kk;
                    const float2 h2 = *(const float2*)&hh[k * 64 + b0];   // LDS.64
                    const unsigned long long hp0 = pack2(h2.x, h2.x);
                    const unsigned long long hp1 = pack2(h2.y, h2.y);
                    const int kw = kq * 128 + k;
                    ulonglong2 w01 = *(const ulonglong2*)&ws[kw][pp * 8];      // bcast
                    ulonglong2 w23 = *(const ulonglong2*)&ws[kw][pp * 8 + 4];  // bcast
                    fma2(aI0, w01.x, hp0); fma2(aI1, w01.x, hp1);
                    fma2(aF0, w01.y, hp0); fma2(aF1, w01.y, hp1);
                    fma2(aG0, w23.x, hp0); fma2(aG1, w23.x, hp1);
                    fma2(aO0, w23.y, hp0); fma2(aO1, w23.y, hp1);
                }
            }
        }

        // ---- 4-way cross-quarter reduction (fixed order) ----
        {
            float v[16];
            const float2 vI0 = unpack2(aI0), vI1 = unpack2(aI1);
            const float2 vF0 = unpack2(aF0), vF1 = unpack2(aF1);
            const float2 vG0 = unpack2(aG0), vG1 = unpack2(aG1);
            const float2 vO0 = unpack2(aO0), vO1 = unpack2(aO1);
            v[0]  = vI0.x; v[2]  = vI0.y; v[1]  = vI1.x; v[3]  = vI1.y;
            v[4]  = vF0.x; v[6]  = vF0.y; v[5]  = vF1.x; v[7]  = vF1.y;
            v[8]  = vG0.x; v[10] = vG0.y; v[9]  = vG1.x; v[11] = vG1.y;
            v[12] = vO0.x; v[14] = vO0.y; v[13] = vO1.x; v[15] = vO1.y;

            if (kq > 0) {
#pragma unroll
                for (int i = 0; i < 16; i++) red[kq - 1][i][pp][jp] = v[i];
            }
            __syncthreads();

            if (kq == 0) {
                float G[16];
#pragma unroll
                for (int i = 0; i < 16; i++)
                    G[i] = ((v[i] + red[0][i][pp][jp]) + red[1][i][pp][jp])
                           + red[2][i][pp][jp] + xwv[i];

                // cell update for 2 units x 2 batches (c in registers)
                const bool m0k = s < len0, m1k = s < len1;
                const int wp = t & 1;
                float hw[2][2];
#pragma unroll
                for (int un = 0; un < 2; un++) {
                    float* cc0 = (un == 0) ? &c00 : &c10;
                    float* cc1 = (un == 0) ? &c01 : &c11;
                    {   // batch b0
                        const float iv = G[0 + un * 2], fv = G[4 + un * 2];
                        const float gv = G[8 + un * 2], ov = G[12 + un * 2];
                        const float cn = sigmf(fv) * (*cc0) + sigmf(iv) * tanhf(gv);
                        const float hn = sigmf(ov) * tanhf(cn);
                        *cc0 = m0k ? cn : *cc0;
                        hw[un][0] = m0k ? hn : 0.f;
                    }
                    {   // batch b1
                        const float iv = G[1 + un * 2], fv = G[5 + un * 2];
                        const float gv = G[9 + un * 2], ov = G[13 + un * 2];
                        const float cn = sigmf(fv) * (*cc1) + sigmf(iv) * tanhf(gv);
                        const float hn = sigmf(ov) * tanhf(cn);
                        *cc1 = m1k ? cn : *cc1;
                        hw[un][1] = m1k ? hn : 0.f;
                    }
                }
                g_ht[dir][wp][u0][b0]     = hw[0][0];
                g_ht[dir][wp][u0][b1]     = hw[0][1];
                g_ht[dir][wp][u0 + 1][b0] = hw[1][0];
                g_ht[dir][wp][u0 + 1][b1] = hw[1][1];
                *(float2*)&g_hbk[s][dir][b0][u0] = make_float2(hw[0][0], hw[1][0]);
                *(float2*)&g_hbk[s][dir][b1][u0] = make_float2(hw[0][1], hw[1][1]);
            }
        }

        // ---- cross-CTA step barrier ----
        if (t < SS - 1) {
            __threadfence();
            __syncthreads();
            if (tid == 0) {
                const unsigned int a = atomicAdd(&g_cnt[cta & 7], 1u);
                if ((a & 15u) == 15u) {
                    const unsigned int r = atomicAdd(&g_root, 1u);
                    if ((r & 7u) == 7u)
                        atomicExch(&g_epoch, (unsigned int)(t + 1));
                }
                while (*(volatile unsigned int*)&g_epoch < (unsigned int)(t + 1))
                    __nanosleep(32);
                __threadfence();
            }
            __syncthreads();
        }
    }
}

// ---------------- K3: emissions feats = h @ w_out^T + b_out ----------------
__global__ __launch_bounds__(256) void k3_feats(
    const float* __restrict__ w_out, const float* __restrict__ b_out)
{
    __shared__ float ws[TT * 1024];   // [t][dir*512 + k]
    for (int i = threadIdx.x; i < TT * 1024; i += 256) ws[i] = w_out[i];
    __syncthreads();

    const int widx = blockIdx.x * 8 + (threadIdx.x >> 5);
    const int lane = threadIdx.x & 31;
    const int s = widx >> 6, b = widx & 63;

    float acc[TT];
#pragma unroll
    for (int t = 0; t < TT; t++) acc[t] = 0.0f;

#pragma unroll
    for (int d = 0; d < 2; d++) {
        const float* hrow = &g_hbk[s][d][b][0];
#pragma unroll 4
        for (int i = 0; i < 16; i++) {
            const int k = lane + i * 32;
            const float hv = hrow[k];
#pragma unroll
            for (int t = 0; t < TT; t++) acc[t] += hv * ws[t * 1024 + d * 512 + k];
        }
    }
#pragma unroll
    for (int t = 0; t < TT; t++) {
        float v = acc[t];
        v += __shfl_xor_sync(0xffffffffu, v, 16);
        v += __shfl_xor_sync(0xffffffffu, v, 8);
        v += __shfl_xor_sync(0xffffffffu, v, 4);
        v += __shfl_xor_sync(0xffffffffu, v, 2);
        v += __shfl_xor_sync(0xffffffffu, v, 1);
        if (lane == t) g_feats[b][s][t] = v + b_out[t];
    }
}

// ---------------- K4: Viterbi decode + backtrace (one warp per batch) ----------------
// Output written as float32 (harness __output__ dtype).
__global__ __launch_bounds__(32) void k4_viterbi(
    const float* __restrict__ start_t, const float* __restrict__ end_t,
    const float* __restrict__ trans, const int* __restrict__ lengths,
    float* __restrict__ out)
{
    const int b = blockIdx.x;
    const int lane = threadIdx.x;
    __shared__ float fe[SS][TT];
    __shared__ float tr[TT][TT];
    __shared__ float sc[TT];
    __shared__ unsigned char bp[SS][TT];

    for (int i = lane; i < SS * TT; i += 32)
        ((float*)fe)[i] = ((const float*)g_feats[b])[i];
    for (int i = lane; i < TT * TT; i += 32)
        ((float*)tr)[i] = trans[i];
    int len = lengths[b];
    if (len < 0) len = 0; if (len > SS) len = SS;
    __syncwarp();
    if (lane < TT) sc[lane] = start_t[lane] + fe[0][lane];
    __syncwarp();

    for (int s = 1; s < SS; ++s) {
        float best = -1e30f; int arg = 0;
        if (lane < TT) {
#pragma unroll
            for (int i = 0; i < TT; i++) {
                const float c = sc[i] + tr[i][lane];
                if (c > best) { best = c; arg = i; }   // first-max, matches jnp.argmax
            }
        }
        __syncwarp();
        if (lane < TT) {
            if (s < len) { sc[lane] = best + fe[s][lane]; bp[s][lane] = (unsigned char)arg; }
            else         { bp[s][lane] = (unsigned char)lane; }
        }
        __syncwarp();
    }

    if (lane == 0) {
        float bestv = -1e30f; int last = 0;
        for (int j = 0; j < TT; j++) {
            const float v = sc[j] + end_t[j];
            if (v > bestv) { bestv = v; last = j; }
        }
        int cur = last;
        for (int s = SS - 1; s >= 1; --s) {
            out[b * SS + s] = (float)((s < len) ? cur : 0);
            cur = bp[s][cur];
        }
        out[b * SS + 0] = (float)cur;
    }
}

// ---------------- host ----------------
static int find_slot(const int* sz, int n, int want, int which, int fallback) {
    int seen = 0;
    for (int i = 0; i < n; i++)
        if (sz[i] == want) { if (seen == which) return i; seen++; }
    return fallback;
}

extern "C" void kernel_launch(void* const* d_in, const int* in_sizes, int n_in,
                              void* d_out, int out_size)
{
    const int i_tok  = find_slot(in_sizes, n_in, SS * BB,      0, 0);
    const int i_len  = find_slot(in_sizes, n_in, BB,           0, 1);
    const int i_emb  = find_slot(in_sizes, n_in, 30000 * EE,   0, 2);
    const int i_wif  = find_slot(in_sizes, n_in, G4 * EE,      0, 3);
    const int i_whf  = find_slot(in_sizes, n_in, G4 * HH,      0, 4);
    const int i_bf   = find_slot(in_sizes, n_in, G4,           0, 5);
    const int i_wib  = find_slot(in_sizes, n_in, G4 * EE,      1, 6);
    const int i_whb  = find_slot(in_sizes, n_in, G4 * HH,      1, 7);
    const int i_bb   = find_slot(in_sizes, n_in, G4,           1, 8);
    const int i_wout = find_slot(in_sizes, n_in, TT * 2 * HH,  0, 9);
    const int i_bout = find_slot(in_sizes, n_in, TT,           0, 10);
    const int i_st   = find_slot(in_sizes, n_in, TT,           1, 11);
    const int i_en   = find_slot(in_sizes, n_in, TT,           2, 12);
    const int i_tr   = find_slot(in_sizes, n_in, TT * TT,      0, 13);

    const int*   tokens  = (const int*)  d_in[i_tok];
    const int*   lens    = (const int*)  d_in[i_len];
    const float* emb     = (const float*)d_in[i_emb];
    const float* wih_f   = (const float*)d_in[i_wif];
    const float* whh_f   = (const float*)d_in[i_whf];
    const float* b_f     = (const float*)d_in[i_bf];
    const float* wih_b   = (const float*)d_in[i_wib];
    const float* whh_b   = (const float*)d_in[i_whb];
    const float* b_b     = (const float*)d_in[i_bb];
    const float* w_out   = (const float*)d_in[i_wout];
    const float* b_out   = (const float*)d_in[i_bout];
    const float* start_t = (const float*)d_in[i_st];
    const float* end_t   = (const float*)d_in[i_en];
    const float* trans   = (const float*)d_in[i_tr];
    float* out = (float*)d_out;

    cudaFuncSetAttribute(k2_persist, cudaFuncAttributeMaxDynamicSharedMemorySize, K2_DSMEM);

    k0_prep<<<dim3(2, HH), HH>>>(whh_f, whh_b);
    k1_proj<<<dim3(64, 256), 256>>>(tokens, emb, wih_f, b_f, wih_b, b_b);
    k2_persist<<<128, 512, K2_DSMEM>>>(lens);
    k3_feats<<<2048, 256>>>(w_out, b_out);
    k4_viterbi<<<64, 32>>>(start_t, end_t, trans, lens, out);
}